// round 14
// baseline (speedup 1.0000x reference)
#include <cuda_runtime.h>
#include <cuda_fp16.h>
#include <math.h>
#include <stdint.h>

#define Rr 16
#define Cc 256
#define Bb 12
#define Ee 768
#define Hh 12
#define Dd 64
#define RD 1024
#define PAIRS 144
#define OUT_ELEMS 37748736
#define PROB_ELEMS 9437184
#define WSZ 589824
#define SCALING 0.03125f

#define KC 64            // k-chunk (halves)
#define ASTR 72          // smem row stride in halves (144B rows, conflict-free)
#define TSZB 18432       // one 128xKC tile in bytes (128*72*2)
#define BUF3B 55296      // 3-tile buffer (split / attn path)
#define BUF2B 36864      // 2-tile buffer (single-pass path)
#define SMEMB 110592     // 2 CTAs/SM (221KB < 228KB)

typedef __half fp16;

// ---------------- scratch (static device globals; no runtime alloc) --------
__device__ __align__(256) fp16 g_xh[OUT_ELEMS];
__device__ __align__(256) fp16 g_wh[4 * WSZ];
__device__ __align__(256) fp16 g_qh[OUT_ELEMS], g_ql[OUT_ELEMS];
__device__ __align__(256) fp16 g_kh[OUT_ELEMS];
__device__ __align__(256) fp16 g_vh[OUT_ELEMS];
__device__ __align__(256) fp16 g_vth[OUT_ELEMS];
__device__ __align__(256) fp16 g_ch[OUT_ELEMS];
__device__ __align__(256) fp16 g_ph2[PROB_ELEMS];
__device__ __align__(256) int   g_bk[Hh * Cc * Cc];

// ---------------- helpers ---------------------------------------------------
__device__ __forceinline__ uint32_t s2u(const void* p) {
    uint32_t a;
    asm("{ .reg .u64 t; cvta.to.shared.u64 t, %1; cvt.u32.u64 %0, t; }" : "=r"(a) : "l"(p));
    return a;
}
__device__ __forceinline__ void cpa16(uint32_t dst, const void* src) {
    asm volatile("cp.async.cg.shared.global [%0], [%1], 16;" :: "r"(dst), "l"(src) : "memory");
}
__device__ __forceinline__ void ldm_x4(uint32_t addr, uint32_t* r) {
    asm volatile("ldmatrix.sync.aligned.m8n8.x4.shared.b16 {%0,%1,%2,%3}, [%4];"
                 : "=r"(r[0]), "=r"(r[1]), "=r"(r[2]), "=r"(r[3]) : "r"(addr));
}
__device__ __forceinline__ void mma16816(float* d, const uint32_t* a, const uint32_t* b) {
    asm volatile("mma.sync.aligned.m16n8k16.row.col.f32.f16.f16.f32 "
                 "{%0,%1,%2,%3}, {%4,%5,%6,%7}, {%8,%9}, {%0,%1,%2,%3};"
                 : "+f"(d[0]), "+f"(d[1]), "+f"(d[2]), "+f"(d[3])
                 : "r"(a[0]), "r"(a[1]), "r"(a[2]), "r"(a[3]), "r"(b[0]), "r"(b[1]));
}
__device__ __forceinline__ uint32_t pack2h(float v0, float v1, uint32_t& lo) {
    fp16 h0 = __float2half_rn(v0), h1 = __float2half_rn(v1);
    float r0 = v0 - __half2float(h0), r1 = v1 - __half2float(h1);
    fp16 l0 = __float2half_rn(r0), l1 = __float2half_rn(r1);
    lo = (uint32_t)__half_as_ushort(l0) | ((uint32_t)__half_as_ushort(l1) << 16);
    return (uint32_t)__half_as_ushort(h0) | ((uint32_t)__half_as_ushort(h1) << 16);
}
__device__ __forceinline__ uint32_t packh(float v0, float v1) {
    __half2 h = __floats2half2_rn(v0, v1);
    return *reinterpret_cast<uint32_t*>(&h);
}

// ---------------- generic warp-mma GEMM core (128x128 tile) -----------------
// SPLIT=false: buffer = [Ah | Bh], 2 buffers, 2-stage. (split path unused here)
__device__ __forceinline__ void issue_chunk(
    const fp16* __restrict__ Ah, int lda,
    const fp16* __restrict__ Bh, int ldb,
    int k0, uint32_t s, int tid)
{
#pragma unroll
    for (int t = 0; t < 4; t++) {
        const int u = t * 256 + tid;
        const int row = u >> 3, c = u & 7;
        const uint32_t d = s + (uint32_t)row * 144 + c * 16;
        cpa16(d,        Ah + (size_t)row * lda + k0 + c * 8);
        cpa16(d + TSZB, Bh + (size_t)row * ldb + k0 + c * 8);
    }
}

__device__ __forceinline__ void mma_all(float acc[4][4][4], uint32_t a[4][4], uint32_t b[2][4]) {
#pragma unroll
    for (int mt = 0; mt < 4; mt++)
#pragma unroll
        for (int nt = 0; nt < 4; nt++)
            mma16816(acc[mt][nt], a[mt], &b[nt >> 1][(nt & 1) * 2]);
}

__device__ __forceinline__ void compute_chunk(uint32_t s, int lane, int wm, int wn,
                                              float acc[4][4][4]) {
    const int g = lane >> 3, r = lane & 7;
    const uint32_t aoff = (uint32_t)(wm * 64 + (g & 1) * 8 + r) * 144 + (g >> 1) * 16;
    const uint32_t boff = (uint32_t)(wn * 32 + (g >> 1) * 8 + r) * 144 + (g & 1) * 16;
#pragma unroll
    for (int kk = 0; kk < 4; kk++) {
        const uint32_t ka = s + aoff + kk * 32;
        const uint32_t kb = s + boff + kk * 32;
        uint32_t a[4][4], b[2][4];
#pragma unroll
        for (int np = 0; np < 2; np++) ldm_x4(kb + TSZB + np * (16 * 144), b[np]);
#pragma unroll
        for (int mt = 0; mt < 4; mt++) ldm_x4(ka + mt * (16 * 144), a[mt]);
        mma_all(acc, a, b);
    }
}

__device__ __forceinline__ void mma_gemm(
    const fp16* __restrict__ Ah, int lda,
    const fp16* __restrict__ Bh, int ldb,
    int K, float acc[4][4][4])
{
    extern __shared__ char smc[];
    const uint32_t sbase = s2u(smc);
    const int tid = threadIdx.x;
    const int lane = tid & 31, wid = tid >> 5;
    const int wm = wid >> 2, wn = wid & 3;
#pragma unroll
    for (int i = 0; i < 4; i++)
#pragma unroll
        for (int j = 0; j < 4; j++)
#pragma unroll
            for (int k2 = 0; k2 < 4; k2++) acc[i][j][k2] = 0.f;

    const int nch = K / KC;
    issue_chunk(Ah, lda, Bh, ldb, 0, sbase, tid);
    asm volatile("cp.async.commit_group;" ::: "memory");
    for (int ch = 0; ch < nch; ch++) {
        asm volatile("cp.async.wait_group 0;" ::: "memory");
        __syncthreads();
        if (ch + 1 < nch) {
            issue_chunk(Ah, lda, Bh, ldb, (ch + 1) * KC,
                        sbase + ((ch + 1) & 1) * BUF2B, tid);
            asm volatile("cp.async.commit_group;" ::: "memory");
        }
        compute_chunk(sbase + (ch & 1) * BUF2B, lane, wm, wn, acc);
    }
}

// ---------------- kernel: weights -> fp16 (hi only), all 4 fused ------------
__global__ __launch_bounds__(256) void k_cvt_w(
    const float* __restrict__ Wq, const float* __restrict__ Wk,
    const float* __restrict__ Wv, const float* __restrict__ Wo)
{
    const int idx = blockIdx.x * 256 + threadIdx.x;
    if (idx >= WSZ / 4) return;
    const int z = blockIdx.y;
    const float* W = (z == 0) ? Wq : (z == 1) ? Wk : (z == 2) ? Wv : Wo;
    float4 v = reinterpret_cast<const float4*>(W)[idx];
    reinterpret_cast<uint2*>(g_wh + (size_t)z * WSZ)[idx] =
        make_uint2(packh(v.x, v.y), packh(v.z, v.w));
}

// ---------------- kernel: x -> fp16 (hi only) -------------------------------
__global__ __launch_bounds__(256) void k_cvt_x(const float* __restrict__ x) {
    const int idx = blockIdx.x * 256 + threadIdx.x;
    if (idx >= OUT_ELEMS / 4) return;
    float4 v = reinterpret_cast<const float4*>(x)[idx];
    reinterpret_cast<uint2*>(g_xh)[idx] =
        make_uint2(packh(v.x, v.y), packh(v.z, v.w));
}

// ---------------- kernel: T5 buckets -> rb row offset -----------------------
__global__ __launch_bounds__(256) void k_bucket(const int* __restrict__ dist) {
    int idx = blockIdx.x * 256 + threadIdx.x;
    if (idx >= Hh * Cc * Cc) return;
    int dv = dist[idx];
    int bkt;
    if (dv < 16) bkt = dv;
    else {
        double t = log((double)dv * (1.0 / 16.0)) * (15.0 / 8.047189562170502);
        int b2 = 16 + (int)t;
        bkt = b2 < 31 ? b2 : 31;
    }
    g_bk[idx] = bkt * Hh;
}

// ---------------- kernel: fused Q/K/V projection (single-pass) --------------
__global__ __launch_bounds__(256) void k_gemm_proj(
    const float* __restrict__ bqp, const float* __restrict__ bkp,
    const float* __restrict__ bvp)
{
    const int z = blockIdx.z;
    const int m0 = blockIdx.y * 128, n0 = blockIdx.x * 128;
    float acc[4][4][4];
    mma_gemm(g_xh + (size_t)m0 * Ee, Ee,
             g_wh + (size_t)z * WSZ + (size_t)n0 * Ee, Ee, Ee, acc);
    const float* bias = (z == 0) ? bqp : (z == 1) ? bkp : bvp;
    fp16* dh = (z == 0) ? g_qh : (z == 1) ? g_kh : g_vh;
    const int lane = threadIdx.x & 31, wid = threadIdx.x >> 5;
    const int mbase = m0 + (wid >> 2) * 64 + (lane >> 2);
    const int nbase = n0 + (wid & 3) * 32 + (lane & 3) * 2;
    const float sc = (z == 0) ? SCALING : 1.0f;
#pragma unroll
    for (int mt = 0; mt < 4; mt++)
#pragma unroll
        for (int rh = 0; rh < 2; rh++) {
            int m = mbase + mt * 16 + rh * 8;
            int r = m / 3072, rem = m % 3072;
            int i = rem / 12, nb = rem % 12;
#pragma unroll
            for (int nt = 0; nt < 4; nt++) {
                int n = nbase + nt * 8;
                int h = n >> 6, d = n & 63;
                float v0 = (acc[mt][nt][rh * 2]     + bias[n])     * sc;
                float v1 = (acc[mt][nt][rh * 2 + 1] + bias[n + 1]) * sc;
                size_t dst = (((size_t)(nb * Hh + h) * Cc) + i) * RD + r * 64 + d;
                if (z == 0) {
                    uint32_t lo, hi = pack2h(v0, v1, lo);
                    *reinterpret_cast<uint32_t*>(dh + dst)   = hi;
                    *reinterpret_cast<uint32_t*>(g_ql + dst) = lo;
                } else {
                    *reinterpret_cast<uint32_t*>(dh + dst) = packh(v0, v1);
                }
            }
        }
}

// ---------------- kernel: transpose V [pair][i][rd] -> [pair][rd][i] --------
__global__ void k_transp() {
    __shared__ unsigned short th[32][33];
    const int p = blockIdx.z;
    const int rd0 = blockIdx.x * 32, i0 = blockIdx.y * 32;
    const unsigned short* sh = reinterpret_cast<const unsigned short*>(g_vh) + (size_t)p * 262144;
    unsigned short* dh = reinterpret_cast<unsigned short*>(g_vth) + (size_t)p * 262144;
    const int tx = threadIdx.x, ty = threadIdx.y;
#pragma unroll
    for (int s = 0; s < 32; s += 8)
        th[ty + s][tx] = sh[(size_t)(i0 + ty + s) * 1024 + rd0 + tx];
    __syncthreads();
#pragma unroll
    for (int s = 0; s < 32; s += 8)
        dh[(size_t)(rd0 + ty + s) * 256 + i0 + tx] = th[tx][ty + s];
}

// ---------------- kernel: FUSED attention scores + bias + softmax -----------
// CTA: 64 (m) x 256 (full j row) per (h,nb) pair. Warp tile 32x64 (2x8 mma
// tiles). q hi/lo split (2-pass A), K hi-only. Softmax in-register with
// 4-lane shfl + cross-warp smem reduce. Writes probs (fp32, output) + g_ph2.
__global__ __launch_bounds__(256, 2) void k_attn_fused(
    const float* __restrict__ rb, float* __restrict__ probs)
{
    extern __shared__ char smc[];
    const uint32_t sbase = s2u(smc);
    const int tid = threadIdx.x;
    const int lane = tid & 31, wid = tid >> 5;
    const int wm = wid >> 2, wn = wid & 3;   // wm 0..1, wn 0..3

    const int m0 = blockIdx.x * 64;
    const int pz = blockIdx.y;
    const int h = pz / Bb, nb = pz % Bb;
    const size_t base = (size_t)(nb * Hh + h) * Cc * RD;
    const fp16* Qh = g_qh + base + (size_t)m0 * RD;
    const fp16* Ql = g_ql + base + (size_t)m0 * RD;
    const fp16* Kh = g_kh + base;

    float acc[2][8][4];
#pragma unroll
    for (int i = 0; i < 2; i++)
#pragma unroll
        for (int j = 0; j < 8; j++)
#pragma unroll
            for (int k2 = 0; k2 < 4; k2++) acc[i][j][k2] = 0.f;

    // ---- mainloop: 16 chunks, 2-stage ----
    // buffer: [Qh 64x72 | Ql 64x72 | Kh 256x72] = 9216 + 9216 + 36864 = 55296
    auto issue = [&](int k0, uint32_t s) {
#pragma unroll
        for (int t = 0; t < 12; t++) {
            const int u = t * 256 + tid;
            if (t < 2) {
                int row = u >> 3, c = u & 7;
                cpa16(s + row * 144 + c * 16, Qh + (size_t)row * RD + k0 + c * 8);
            } else if (t < 4) {
                int u2 = u - 512, row = u2 >> 3, c = u2 & 7;
                cpa16(s + 9216 + row * 144 + c * 16, Ql + (size_t)row * RD + k0 + c * 8);
            } else {
                int u2 = u - 1024, row = u2 >> 3, c = u2 & 7;
                cpa16(s + 18432 + row * 144 + c * 16, Kh + (size_t)row * RD + k0 + c * 8);
            }
        }
    };

    const int g = lane >> 3, r = lane & 7;
    const uint32_t aoff = (uint32_t)(wm * 32 + (g & 1) * 8 + r) * 144 + (g >> 1) * 16;
    const uint32_t boff = (uint32_t)(wn * 64 + (g >> 1) * 8 + r) * 144 + (g & 1) * 16;

    issue(0, sbase);
    asm volatile("cp.async.commit_group;" ::: "memory");
    for (int ch = 0; ch < 16; ch++) {
        asm volatile("cp.async.wait_group 0;" ::: "memory");
        __syncthreads();
        if (ch + 1 < 16) {
            issue((ch + 1) * KC, sbase + ((ch + 1) & 1) * BUF3B);
            asm volatile("cp.async.commit_group;" ::: "memory");
        }
        const uint32_t s = sbase + (ch & 1) * BUF3B;
#pragma unroll
        for (int kk = 0; kk < 4; kk++) {
            const uint32_t ka = s + aoff + kk * 32;
            const uint32_t kb = s + 18432 + boff + kk * 32;
            uint32_t a[2][4], b[4][4];
#pragma unroll
            for (int np = 0; np < 4; np++) ldm_x4(kb + np * (16 * 144), b[np]);
            // pass 1: Qh x K
#pragma unroll
            for (int mt = 0; mt < 2; mt++) ldm_x4(ka + mt * (16 * 144), a[mt]);
#pragma unroll
            for (int mt = 0; mt < 2; mt++)
#pragma unroll
                for (int nt = 0; nt < 8; nt++)
                    mma16816(acc[mt][nt], a[mt], &b[nt >> 1][(nt & 1) * 2]);
            // pass 2: Ql x K
#pragma unroll
            for (int mt = 0; mt < 2; mt++) ldm_x4(ka + 9216 + mt * (16 * 144), a[mt]);
#pragma unroll
            for (int mt = 0; mt < 2; mt++)
#pragma unroll
                for (int nt = 0; nt < 8; nt++)
                    mma16816(acc[mt][nt], a[mt], &b[nt >> 1][(nt & 1) * 2]);
        }
    }
    __syncthreads();   // mainloop smem no longer needed; reuse for reductions

    // ---- bias + softmax ----
    float* redA = reinterpret_cast<float*>(smc);          // [64][4]
    float* redB = reinterpret_cast<float*>(smc) + 1024;   // [64][4]

    // 1) add bias, row max (local 16 vals -> 4-lane reduce -> smem)
#pragma unroll
    for (int mt = 0; mt < 2; mt++)
#pragma unroll
        for (int rh = 0; rh < 2; rh++) {
            const int lrow = wm * 32 + mt * 16 + rh * 8 + (lane >> 2);
            const int ii = m0 + lrow;
            const int* bkrow = g_bk + (h * Cc + ii) * Cc;
            float mx = -1e30f;
#pragma unroll
            for (int nt = 0; nt < 8; nt++) {
                int j = wn * 64 + nt * 8 + (lane & 3) * 2;
                float v0 = acc[mt][nt][rh * 2]     + rb[bkrow[j]     + nb];
                float v1 = acc[mt][nt][rh * 2 + 1] + rb[bkrow[j + 1] + nb];
                acc[mt][nt][rh * 2] = v0; acc[mt][nt][rh * 2 + 1] = v1;
                mx = fmaxf(mx, fmaxf(v0, v1));
            }
            mx = fmaxf(mx, __shfl_xor_sync(0xffffffffu, mx, 1));
            mx = fmaxf(mx, __shfl_xor_sync(0xffffffffu, mx, 2));
            if ((lane & 3) == 0) redA[lrow * 4 + wn] = mx;
        }
    __syncthreads();

    // 2) exp + row sum
#pragma unroll
    for (int mt = 0; mt < 2; mt++)
#pragma unroll
        for (int rh = 0; rh < 2; rh++) {
            const int lrow = wm * 32 + mt * 16 + rh * 8 + (lane >> 2);
            float fm = fmaxf(fmaxf(redA[lrow * 4 + 0], redA[lrow * 4 + 1]),
                             fmaxf(redA[lrow * 4 + 2], redA[lrow * 4 + 3]));
            float sum = 0.f;
#pragma unroll
            for (int nt = 0; nt < 8; nt++) {
                float v0 = expf(acc[mt][nt][rh * 2]     - fm);
                float v1 = expf(acc[mt][nt][rh * 2 + 1] - fm);
                acc[mt][nt][rh * 2] = v0; acc[mt][nt][rh * 2 + 1] = v1;
                sum += v0 + v1;
            }
            sum += __shfl_xor_sync(0xffffffffu, sum, 1);
            sum += __shfl_xor_sync(0xffffffffu, sum, 2);
            if ((lane & 3) == 0) redB[lrow * 4 + wn] = sum;
        }
    __syncthreads();

    // 3) normalize + write probs (fp32 output) and g_ph2 (fp16)
#pragma unroll
    for (int mt = 0; mt < 2; mt++)
#pragma unroll
        for (int rh = 0; rh < 2; rh++) {
            const int lrow = wm * 32 + mt * 16 + rh * 8 + (lane >> 2);
            const int ii = m0 + lrow;
            const float inv = 1.0f / (redB[lrow * 4 + 0] + redB[lrow * 4 + 1] +
                                      redB[lrow * 4 + 2] + redB[lrow * 4 + 3]);
            float* prow = probs + ((size_t)(h * Bb + nb) * Cc + ii) * Cc;
            fp16* hrow = g_ph2 + ((size_t)(h * Bb + nb) * Cc + ii) * Cc;
#pragma unroll
            for (int nt = 0; nt < 8; nt++) {
                int j = wn * 64 + nt * 8 + (lane & 3) * 2;
                float v0 = acc[mt][nt][rh * 2]     * inv;
                float v1 = acc[mt][nt][rh * 2 + 1] * inv;
                *reinterpret_cast<float2*>(prow + j) = make_float2(v0, v1);
                *reinterpret_cast<uint32_t*>(hrow + j) = packh(v0, v1);
            }
        }
}

// ---------------- kernel: ctx = probs @ V (single pass) ---------------------
__global__ __launch_bounds__(256) void k_gemm_ctx() {
    const int z = blockIdx.z;
    const int h = z / Bb, nb = z % Bb;
    const int m0 = blockIdx.y * 128, n0 = blockIdx.x * 128;
    const size_t pb = (size_t)(h * Bb + nb) * Cc * Cc;
    const size_t vb = (size_t)(nb * Hh + h) * Cc * RD;
    float acc[4][4][4];
    mma_gemm(g_ph2 + pb + (size_t)m0 * Cc, Cc,
             g_vth + vb + (size_t)n0 * Cc, Cc, Cc, acc);
    const int lane = threadIdx.x & 31, wid = threadIdx.x >> 5;
    const int mbase = m0 + (wid >> 2) * 64 + (lane >> 2);
    const int nbase = n0 + (wid & 3) * 32 + (lane & 3) * 2;
#pragma unroll
    for (int mt = 0; mt < 4; mt++)
#pragma unroll
        for (int rh = 0; rh < 2; rh++) {
            int i = mbase + mt * 16 + rh * 8;
#pragma unroll
            for (int nt = 0; nt < 4; nt++) {
                int rd = nbase + nt * 8;
                int r = rd >> 6, d = rd & 63;
                size_t dst = (((size_t)(r * Cc + i) * Bb) + nb) * Ee + h * Dd + d;
                *reinterpret_cast<uint32_t*>(g_ch + dst) =
                    packh(acc[mt][nt][rh * 2], acc[mt][nt][rh * 2 + 1]);
            }
        }
}

// ---------------- kernel: out = ctx @ Wo^T + bo (single pass) ---------------
__global__ __launch_bounds__(256) void k_gemm_out(const float* __restrict__ bo,
                                                  float* __restrict__ out) {
    const int m0 = blockIdx.y * 128, n0 = blockIdx.x * 128;
    float acc[4][4][4];
    mma_gemm(g_ch + (size_t)m0 * Ee, Ee,
             g_wh + 3 * (size_t)WSZ + (size_t)n0 * Ee, Ee, Ee, acc);
    const int lane = threadIdx.x & 31, wid = threadIdx.x >> 5;
    const int mbase = m0 + (wid >> 2) * 64 + (lane >> 2);
    const int nbase = n0 + (wid & 3) * 32 + (lane & 3) * 2;
#pragma unroll
    for (int mt = 0; mt < 4; mt++)
#pragma unroll
        for (int rh = 0; rh < 2; rh++) {
            int m = mbase + mt * 16 + rh * 8;
#pragma unroll
            for (int nt = 0; nt < 4; nt++) {
                int n = nbase + nt * 8;
                float2 o;
                o.x = acc[mt][nt][rh * 2]     + bo[n];
                o.y = acc[mt][nt][rh * 2 + 1] + bo[n + 1];
                *reinterpret_cast<float2*>(out + (size_t)m * Ee + n) = o;
            }
        }
}

// ---------------------------------------------------------------------------
extern "C" void kernel_launch(void* const* d_in, const int* in_sizes, int n_in,
                              void* d_out, int out_size)
{
    const float* x  = (const float*)d_in[0];
    const int*   ds = (const int*)  d_in[1];
    const float* Wq = (const float*)d_in[2];
    const float* bq = (const float*)d_in[3];
    const float* Wk = (const float*)d_in[4];
    const float* bk = (const float*)d_in[5];
    const float* Wv = (const float*)d_in[6];
    const float* bv = (const float*)d_in[7];
    const float* Wo = (const float*)d_in[8];
    const float* bo = (const float*)d_in[9];
    const float* rb = (const float*)d_in[10];
    float* out   = (float*)d_out;
    float* probs = out + OUT_ELEMS;

    static int smem_set = 0;
    if (!smem_set) {
        cudaFuncSetAttribute(k_gemm_proj, cudaFuncAttributeMaxDynamicSharedMemorySize, SMEMB);
        cudaFuncSetAttribute(k_attn_fused, cudaFuncAttributeMaxDynamicSharedMemorySize, SMEMB);
        cudaFuncSetAttribute(k_gemm_ctx,  cudaFuncAttributeMaxDynamicSharedMemorySize, SMEMB);
        cudaFuncSetAttribute(k_gemm_out,  cudaFuncAttributeMaxDynamicSharedMemorySize, SMEMB);
        smem_set = 1;
    }

    // launch order chosen so capture index 3 == k_gemm_proj
    k_cvt_w<<<dim3((WSZ / 4 + 255) / 256, 4), 256>>>(Wq, Wk, Wv, Wo);
    k_cvt_x<<<(OUT_ELEMS / 4 + 255) / 256, 256>>>(x);
    k_bucket<<<(Hh * Cc * Cc + 255) / 256, 256>>>(ds);

    k_gemm_proj<<<dim3(6, 384, 3), 256, SMEMB>>>(bq, bk, bv);
    k_transp<<<dim3(32, 8, 144), dim3(32, 8)>>>();
    k_attn_fused<<<dim3(4, PAIRS), 256, SMEMB>>>(rb, probs);
    k_gemm_ctx<<<dim3(8, 2, PAIRS), 256, SMEMB>>>();
    k_gemm_out<<<dim3(6, 384), 256, SMEMB>>>(bo, out);
}

// round 15
// speedup vs baseline: 1.5199x; 1.5199x over previous
#include <cuda_runtime.h>
#include <cuda_fp16.h>
#include <math.h>
#include <stdint.h>

#define Rr 16
#define Cc 256
#define Bb 12
#define Ee 768
#define Hh 12
#define Dd 64
#define RD 1024
#define PAIRS 144
#define OUT_ELEMS 37748736
#define PROB_ELEMS 9437184
#define WSZ 589824
#define SCALING 0.03125f

#define KC 64            // k-chunk (halves)
#define ASTR 72          // smem row stride in halves (144B rows, conflict-free)
#define TSZB 18432       // one 128xKC tile in bytes (128*72*2)
#define BUFB 55296       // 3-tile buffer stride (R12 geometry; B at +2*TSZB)
#define SMEMB 110592     // 2 buffers -> 2 CTAs/SM (221KB < 228KB)

typedef __half fp16;

// ---------------- scratch (static device globals; no runtime alloc) --------
__device__ __align__(256) fp16 g_xh[OUT_ELEMS];
__device__ __align__(256) fp16 g_wh[4 * WSZ];
__device__ __align__(256) fp16 g_qh[OUT_ELEMS], g_ql[OUT_ELEMS];
__device__ __align__(256) fp16 g_kh[OUT_ELEMS];
__device__ __align__(256) fp16 g_vh[OUT_ELEMS];
__device__ __align__(256) fp16 g_vth[OUT_ELEMS];
__device__ __align__(256) fp16 g_ch[OUT_ELEMS];
__device__ __align__(256) fp16 g_ph2[PROB_ELEMS];
__device__ __align__(256) int   g_bk[Hh * Cc * Cc];

// ---------------- helpers ---------------------------------------------------
__device__ __forceinline__ uint32_t s2u(const void* p) {
    uint32_t a;
    asm("{ .reg .u64 t; cvta.to.shared.u64 t, %1; cvt.u32.u64 %0, t; }" : "=r"(a) : "l"(p));
    return a;
}
__device__ __forceinline__ void cpa16(uint32_t dst, const void* src) {
    asm volatile("cp.async.cg.shared.global [%0], [%1], 16;" :: "r"(dst), "l"(src) : "memory");
}
__device__ __forceinline__ void ldm_x4(uint32_t addr, uint32_t* r) {
    asm volatile("ldmatrix.sync.aligned.m8n8.x4.shared.b16 {%0,%1,%2,%3}, [%4];"
                 : "=r"(r[0]), "=r"(r[1]), "=r"(r[2]), "=r"(r[3]) : "r"(addr));
}
__device__ __forceinline__ void mma16816(float* d, const uint32_t* a, const uint32_t* b) {
    asm volatile("mma.sync.aligned.m16n8k16.row.col.f32.f16.f16.f32 "
                 "{%0,%1,%2,%3}, {%4,%5,%6,%7}, {%8,%9}, {%0,%1,%2,%3};"
                 : "+f"(d[0]), "+f"(d[1]), "+f"(d[2]), "+f"(d[3])
                 : "r"(a[0]), "r"(a[1]), "r"(a[2]), "r"(a[3]), "r"(b[0]), "r"(b[1]));
}
__device__ __forceinline__ uint32_t pack2h(float v0, float v1, uint32_t& lo) {
    fp16 h0 = __float2half_rn(v0), h1 = __float2half_rn(v1);
    float r0 = v0 - __half2float(h0), r1 = v1 - __half2float(h1);
    fp16 l0 = __float2half_rn(r0), l1 = __float2half_rn(r1);
    lo = (uint32_t)__half_as_ushort(l0) | ((uint32_t)__half_as_ushort(l1) << 16);
    return (uint32_t)__half_as_ushort(h0) | ((uint32_t)__half_as_ushort(h1) << 16);
}
__device__ __forceinline__ uint32_t packh(float v0, float v1) {
    __half2 h = __floats2half2_rn(v0, v1);
    return *reinterpret_cast<uint32_t*>(&h);
}

// ---------------- R12 warp-mma GEMM core (exact 537us-proj geometry) --------
// Buffer: [Ah | (dead) | Bh], B at +2*TSZB, buffer stride BUFB, 2-stage.
__device__ __forceinline__ void issue_chunk(
    const fp16* __restrict__ Ah, int lda,
    const fp16* __restrict__ Bh, int ldb,
    int k0, uint32_t s, int tid)
{
#pragma unroll
    for (int t = 0; t < 4; t++) {
        const int u = t * 256 + tid;         // 0..1023
        const int row = u >> 3, c = u & 7;   // 16B unit in a 128B row
        const uint32_t d = s + (uint32_t)row * 144 + c * 16;
        cpa16(d,            Ah + (size_t)row * lda + k0 + c * 8);
        cpa16(d + 2 * TSZB, Bh + (size_t)row * ldb + k0 + c * 8);
    }
}

__device__ __forceinline__ void mma_all(float acc[4][4][4], uint32_t a[4][4], uint32_t b[2][4]) {
#pragma unroll
    for (int mt = 0; mt < 4; mt++)
#pragma unroll
        for (int nt = 0; nt < 4; nt++)
            mma16816(acc[mt][nt], a[mt], &b[nt >> 1][(nt & 1) * 2]);
}

__device__ __forceinline__ void compute_chunk(uint32_t s, int lane, int wm, int wn,
                                              float acc[4][4][4]) {
    const int g = lane >> 3, r = lane & 7;
    const uint32_t aoff = (uint32_t)(wm * 64 + (g & 1) * 8 + r) * 144 + (g >> 1) * 16;
    const uint32_t boff = (uint32_t)(wn * 32 + (g >> 1) * 8 + r) * 144 + (g & 1) * 16;
#pragma unroll
    for (int kk = 0; kk < 4; kk++) {
        const uint32_t ka = s + aoff + kk * 32;
        const uint32_t kb = s + boff + kk * 32;
        uint32_t a[4][4], b[2][4];
#pragma unroll
        for (int np = 0; np < 2; np++) ldm_x4(kb + 2 * TSZB + np * (16 * 144), b[np]);
#pragma unroll
        for (int mt = 0; mt < 4; mt++) ldm_x4(ka + mt * (16 * 144), a[mt]);
        mma_all(acc, a, b);
    }
}

__device__ __forceinline__ void mma_gemm(
    const fp16* __restrict__ Ah, int lda,
    const fp16* __restrict__ Bh, int ldb,
    int K, float acc[4][4][4])
{
    extern __shared__ char smc[];
    const uint32_t sbase = s2u(smc);
    const int tid = threadIdx.x;
    const int lane = tid & 31, wid = tid >> 5;
    const int wm = wid >> 2, wn = wid & 3;
#pragma unroll
    for (int i = 0; i < 4; i++)
#pragma unroll
        for (int j = 0; j < 4; j++)
#pragma unroll
            for (int k2 = 0; k2 < 4; k2++) acc[i][j][k2] = 0.f;

    const int nch = K / KC;
    issue_chunk(Ah, lda, Bh, ldb, 0, sbase, tid);
    asm volatile("cp.async.commit_group;" ::: "memory");
    for (int ch = 0; ch < nch; ch++) {
        asm volatile("cp.async.wait_group 0;" ::: "memory");
        __syncthreads();
        if (ch + 1 < nch) {
            issue_chunk(Ah, lda, Bh, ldb, (ch + 1) * KC,
                        sbase + ((ch + 1) & 1) * BUFB, tid);
            asm volatile("cp.async.commit_group;" ::: "memory");
        }
        compute_chunk(sbase + (ch & 1) * BUFB, lane, wm, wn, acc);
    }
}

// ---------------- kernel: weights -> fp16 (hi only), all 4 fused ------------
__global__ __launch_bounds__(256) void k_cvt_w(
    const float* __restrict__ Wq, const float* __restrict__ Wk,
    const float* __restrict__ Wv, const float* __restrict__ Wo)
{
    const int idx = blockIdx.x * 256 + threadIdx.x;
    if (idx >= WSZ / 4) return;
    const int z = blockIdx.y;
    const float* W = (z == 0) ? Wq : (z == 1) ? Wk : (z == 2) ? Wv : Wo;
    float4 v = reinterpret_cast<const float4*>(W)[idx];
    reinterpret_cast<uint2*>(g_wh + (size_t)z * WSZ)[idx] =
        make_uint2(packh(v.x, v.y), packh(v.z, v.w));
}

// ---------------- kernel: x -> fp16 (hi only) -------------------------------
__global__ __launch_bounds__(256) void k_cvt_x(const float* __restrict__ x) {
    const int idx = blockIdx.x * 256 + threadIdx.x;
    if (idx >= OUT_ELEMS / 4) return;
    float4 v = reinterpret_cast<const float4*>(x)[idx];
    reinterpret_cast<uint2*>(g_xh)[idx] =
        make_uint2(packh(v.x, v.y), packh(v.z, v.w));
}

// ---------------- kernel: T5 buckets -> rb row offset -----------------------
__global__ __launch_bounds__(256) void k_bucket(const int* __restrict__ dist) {
    int idx = blockIdx.x * 256 + threadIdx.x;
    if (idx >= Hh * Cc * Cc) return;
    int dv = dist[idx];
    int bkt;
    if (dv < 16) bkt = dv;
    else {
        double t = log((double)dv * (1.0 / 16.0)) * (15.0 / 8.047189562170502);
        int b2 = 16 + (int)t;
        bkt = b2 < 31 ? b2 : 31;
    }
    g_bk[idx] = bkt * Hh;
}

// ---------------- kernel: fused Q/K/V projection (single-pass) --------------
__global__ __launch_bounds__(256) void k_gemm_proj(
    const float* __restrict__ bqp, const float* __restrict__ bkp,
    const float* __restrict__ bvp)
{
    const int z = blockIdx.z;
    const int m0 = blockIdx.y * 128, n0 = blockIdx.x * 128;
    float acc[4][4][4];
    mma_gemm(g_xh + (size_t)m0 * Ee, Ee,
             g_wh + (size_t)z * WSZ + (size_t)n0 * Ee, Ee, Ee, acc);
    const float* bias = (z == 0) ? bqp : (z == 1) ? bkp : bvp;
    fp16* dh = (z == 0) ? g_qh : (z == 1) ? g_kh : g_vh;
    const int lane = threadIdx.x & 31, wid = threadIdx.x >> 5;
    const int mbase = m0 + (wid >> 2) * 64 + (lane >> 2);
    const int nbase = n0 + (wid & 3) * 32 + (lane & 3) * 2;
    const float sc = (z == 0) ? SCALING : 1.0f;
#pragma unroll
    for (int mt = 0; mt < 4; mt++)
#pragma unroll
        for (int rh = 0; rh < 2; rh++) {
            int m = mbase + mt * 16 + rh * 8;
            int r = m / 3072, rem = m % 3072;
            int i = rem / 12, nb = rem % 12;
#pragma unroll
            for (int nt = 0; nt < 4; nt++) {
                int n = nbase + nt * 8;
                int h = n >> 6, d = n & 63;
                float v0 = (acc[mt][nt][rh * 2]     + bias[n])     * sc;
                float v1 = (acc[mt][nt][rh * 2 + 1] + bias[n + 1]) * sc;
                size_t dst = (((size_t)(nb * Hh + h) * Cc) + i) * RD + r * 64 + d;
                if (z == 0) {
                    uint32_t lo, hi = pack2h(v0, v1, lo);
                    *reinterpret_cast<uint32_t*>(dh + dst)   = hi;
                    *reinterpret_cast<uint32_t*>(g_ql + dst) = lo;
                } else {
                    *reinterpret_cast<uint32_t*>(dh + dst) = packh(v0, v1);
                }
            }
        }
}

// ---------------- kernel: transpose V [pair][i][rd] -> [pair][rd][i] --------
__global__ void k_transp() {
    __shared__ unsigned short th[32][33];
    const int p = blockIdx.z;
    const int rd0 = blockIdx.x * 32, i0 = blockIdx.y * 32;
    const unsigned short* sh = reinterpret_cast<const unsigned short*>(g_vh) + (size_t)p * 262144;
    unsigned short* dh = reinterpret_cast<unsigned short*>(g_vth) + (size_t)p * 262144;
    const int tx = threadIdx.x, ty = threadIdx.y;
#pragma unroll
    for (int s = 0; s < 32; s += 8)
        th[ty + s][tx] = sh[(size_t)(i0 + ty + s) * 1024 + rd0 + tx];
    __syncthreads();
#pragma unroll
    for (int s = 0; s < 32; s += 8)
        dh[(size_t)(rd0 + ty + s) * 256 + i0 + tx] = th[tx][ty + s];
}

// ---------------- kernel: FUSED attention scores + bias + softmax -----------
// CTA: 64 (m) x 256 (full j row) per (h,nb). q hi/lo 2-pass, K hi-only.
// Softmax in-register; writes probs (fp32 output) + g_ph2 (fp16).
__global__ __launch_bounds__(256, 2) void k_attn_fused(
    const float* __restrict__ rb, float* __restrict__ probs)
{
    extern __shared__ char smc[];
    const uint32_t sbase = s2u(smc);
    const int tid = threadIdx.x;
    const int lane = tid & 31, wid = tid >> 5;
    const int wm = wid >> 2, wn = wid & 3;

    const int m0 = blockIdx.x * 64;
    const int pz = blockIdx.y;
    const int h = pz / Bb, nb = pz % Bb;
    const size_t base = (size_t)(nb * Hh + h) * Cc * RD;
    const fp16* Qh = g_qh + base + (size_t)m0 * RD;
    const fp16* Ql = g_ql + base + (size_t)m0 * RD;
    const fp16* Kh = g_kh + base;

    float acc[2][8][4];
#pragma unroll
    for (int i = 0; i < 2; i++)
#pragma unroll
        for (int j = 0; j < 8; j++)
#pragma unroll
            for (int k2 = 0; k2 < 4; k2++) acc[i][j][k2] = 0.f;

    // buffer: [Qh 64x72 | Ql 64x72 | Kh 256x72] = 55296 bytes, 2 buffers
    auto issue = [&](int k0, uint32_t s) {
#pragma unroll
        for (int t = 0; t < 12; t++) {
            const int u = t * 256 + tid;
            if (t < 2) {
                int row = u >> 3, c = u & 7;
                cpa16(s + row * 144 + c * 16, Qh + (size_t)row * RD + k0 + c * 8);
            } else if (t < 4) {
                int u2 = u - 512, row = u2 >> 3, c = u2 & 7;
                cpa16(s + 9216 + row * 144 + c * 16, Ql + (size_t)row * RD + k0 + c * 8);
            } else {
                int u2 = u - 1024, row = u2 >> 3, c = u2 & 7;
                cpa16(s + 18432 + row * 144 + c * 16, Kh + (size_t)row * RD + k0 + c * 8);
            }
        }
    };

    const int g = lane >> 3, r = lane & 7;
    const uint32_t aoff = (uint32_t)(wm * 32 + (g & 1) * 8 + r) * 144 + (g >> 1) * 16;
    const uint32_t boff = (uint32_t)(wn * 64 + (g >> 1) * 8 + r) * 144 + (g & 1) * 16;

    issue(0, sbase);
    asm volatile("cp.async.commit_group;" ::: "memory");
    for (int ch = 0; ch < 16; ch++) {
        asm volatile("cp.async.wait_group 0;" ::: "memory");
        __syncthreads();
        if (ch + 1 < 16) {
            issue((ch + 1) * KC, sbase + ((ch + 1) & 1) * BUFB);
            asm volatile("cp.async.commit_group;" ::: "memory");
        }
        const uint32_t s = sbase + (ch & 1) * BUFB;
#pragma unroll
        for (int kk = 0; kk < 4; kk++) {
            const uint32_t ka = s + aoff + kk * 32;
            const uint32_t kb = s + 18432 + boff + kk * 32;
            uint32_t a[2][4], b[4][4];
#pragma unroll
            for (int np = 0; np < 4; np++) ldm_x4(kb + np * (16 * 144), b[np]);
#pragma unroll
            for (int mt = 0; mt < 2; mt++) ldm_x4(ka + mt * (16 * 144), a[mt]);
#pragma unroll
            for (int mt = 0; mt < 2; mt++)
#pragma unroll
                for (int nt = 0; nt < 8; nt++)
                    mma16816(acc[mt][nt], a[mt], &b[nt >> 1][(nt & 1) * 2]);
#pragma unroll
            for (int mt = 0; mt < 2; mt++) ldm_x4(ka + 9216 + mt * (16 * 144), a[mt]);
#pragma unroll
            for (int mt = 0; mt < 2; mt++)
#pragma unroll
                for (int nt = 0; nt < 8; nt++)
                    mma16816(acc[mt][nt], a[mt], &b[nt >> 1][(nt & 1) * 2]);
        }
    }
    __syncthreads();

    // ---- bias + softmax ----
    float* redA = reinterpret_cast<float*>(smc);          // [64][4]
    float* redB = reinterpret_cast<float*>(smc) + 1024;   // [64][4]

#pragma unroll
    for (int mt = 0; mt < 2; mt++)
#pragma unroll
        for (int rh = 0; rh < 2; rh++) {
            const int lrow = wm * 32 + mt * 16 + rh * 8 + (lane >> 2);
            const int ii = m0 + lrow;
            const int* bkrow = g_bk + (h * Cc + ii) * Cc;
            float mx = -1e30f;
#pragma unroll
            for (int nt = 0; nt < 8; nt++) {
                int j = wn * 64 + nt * 8 + (lane & 3) * 2;
                float v0 = acc[mt][nt][rh * 2]     + rb[bkrow[j]     + nb];
                float v1 = acc[mt][nt][rh * 2 + 1] + rb[bkrow[j + 1] + nb];
                acc[mt][nt][rh * 2] = v0; acc[mt][nt][rh * 2 + 1] = v1;
                mx = fmaxf(mx, fmaxf(v0, v1));
            }
            mx = fmaxf(mx, __shfl_xor_sync(0xffffffffu, mx, 1));
            mx = fmaxf(mx, __shfl_xor_sync(0xffffffffu, mx, 2));
            if ((lane & 3) == 0) redA[lrow * 4 + wn] = mx;
        }
    __syncthreads();

#pragma unroll
    for (int mt = 0; mt < 2; mt++)
#pragma unroll
        for (int rh = 0; rh < 2; rh++) {
            const int lrow = wm * 32 + mt * 16 + rh * 8 + (lane >> 2);
            float fm = fmaxf(fmaxf(redA[lrow * 4 + 0], redA[lrow * 4 + 1]),
                             fmaxf(redA[lrow * 4 + 2], redA[lrow * 4 + 3]));
            float sum = 0.f;
#pragma unroll
            for (int nt = 0; nt < 8; nt++) {
                float v0 = expf(acc[mt][nt][rh * 2]     - fm);
                float v1 = expf(acc[mt][nt][rh * 2 + 1] - fm);
                acc[mt][nt][rh * 2] = v0; acc[mt][nt][rh * 2 + 1] = v1;
                sum += v0 + v1;
            }
            sum += __shfl_xor_sync(0xffffffffu, sum, 1);
            sum += __shfl_xor_sync(0xffffffffu, sum, 2);
            if ((lane & 3) == 0) redB[lrow * 4 + wn] = sum;
        }
    __syncthreads();

#pragma unroll
    for (int mt = 0; mt < 2; mt++)
#pragma unroll
        for (int rh = 0; rh < 2; rh++) {
            const int lrow = wm * 32 + mt * 16 + rh * 8 + (lane >> 2);
            const int ii = m0 + lrow;
            const float inv = 1.0f / (redB[lrow * 4 + 0] + redB[lrow * 4 + 1] +
                                      redB[lrow * 4 + 2] + redB[lrow * 4 + 3]);
            float* prow = probs + ((size_t)(h * Bb + nb) * Cc + ii) * Cc;
            fp16* hrow = g_ph2 + ((size_t)(h * Bb + nb) * Cc + ii) * Cc;
#pragma unroll
            for (int nt = 0; nt < 8; nt++) {
                int j = wn * 64 + nt * 8 + (lane & 3) * 2;
                float v0 = acc[mt][nt][rh * 2]     * inv;
                float v1 = acc[mt][nt][rh * 2 + 1] * inv;
                *reinterpret_cast<float2*>(prow + j) = make_float2(v0, v1);
                *reinterpret_cast<uint32_t*>(hrow + j) = packh(v0, v1);
            }
        }
}

// ---------------- kernel: ctx = probs @ V (single pass) ---------------------
__global__ __launch_bounds__(256) void k_gemm_ctx() {
    const int z = blockIdx.z;
    const int h = z / Bb, nb = z % Bb;
    const int m0 = blockIdx.y * 128, n0 = blockIdx.x * 128;
    const size_t pb = (size_t)(h * Bb + nb) * Cc * Cc;
    const size_t vb = (size_t)(nb * Hh + h) * Cc * RD;
    float acc[4][4][4];
    mma_gemm(g_ph2 + pb + (size_t)m0 * Cc, Cc,
             g_vth + vb + (size_t)n0 * Cc, Cc, Cc, acc);
    const int lane = threadIdx.x & 31, wid = threadIdx.x >> 5;
    const int mbase = m0 + (wid >> 2) * 64 + (lane >> 2);
    const int nbase = n0 + (wid & 3) * 32 + (lane & 3) * 2;
#pragma unroll
    for (int mt = 0; mt < 4; mt++)
#pragma unroll
        for (int rh = 0; rh < 2; rh++) {
            int i = mbase + mt * 16 + rh * 8;
#pragma unroll
            for (int nt = 0; nt < 4; nt++) {
                int rd = nbase + nt * 8;
                int r = rd >> 6, d = rd & 63;
                size_t dst = (((size_t)(r * Cc + i) * Bb) + nb) * Ee + h * Dd + d;
                *reinterpret_cast<uint32_t*>(g_ch + dst) =
                    packh(acc[mt][nt][rh * 2], acc[mt][nt][rh * 2 + 1]);
            }
        }
}

// ---------------- kernel: out = ctx @ Wo^T + bo (single pass) ---------------
__global__ __launch_bounds__(256) void k_gemm_out(const float* __restrict__ bo,
                                                  float* __restrict__ out) {
    const int m0 = blockIdx.y * 128, n0 = blockIdx.x * 128;
    float acc[4][4][4];
    mma_gemm(g_ch + (size_t)m0 * Ee, Ee,
             g_wh + 3 * (size_t)WSZ + (size_t)n0 * Ee, Ee, Ee, acc);
    const int lane = threadIdx.x & 31, wid = threadIdx.x >> 5;
    const int mbase = m0 + (wid >> 2) * 64 + (lane >> 2);
    const int nbase = n0 + (wid & 3) * 32 + (lane & 3) * 2;
#pragma unroll
    for (int mt = 0; mt < 4; mt++)
#pragma unroll
        for (int rh = 0; rh < 2; rh++) {
            int m = mbase + mt * 16 + rh * 8;
#pragma unroll
            for (int nt = 0; nt < 4; nt++) {
                int n = nbase + nt * 8;
                float2 o;
                o.x = acc[mt][nt][rh * 2]     + bo[n];
                o.y = acc[mt][nt][rh * 2 + 1] + bo[n + 1];
                *reinterpret_cast<float2*>(out + (size_t)m * Ee + n) = o;
            }
        }
}

// ---------------------------------------------------------------------------
extern "C" void kernel_launch(void* const* d_in, const int* in_sizes, int n_in,
                              void* d_out, int out_size)
{
    const float* x  = (const float*)d_in[0];
    const int*   ds = (const int*)  d_in[1];
    const float* Wq = (const float*)d_in[2];
    const float* bq = (const float*)d_in[3];
    const float* Wk = (const float*)d_in[4];
    const float* bk = (const float*)d_in[5];
    const float* Wv = (const float*)d_in[6];
    const float* bv = (const float*)d_in[7];
    const float* Wo = (const float*)d_in[8];
    const float* bo = (const float*)d_in[9];
    const float* rb = (const float*)d_in[10];
    float* out   = (float*)d_out;
    float* probs = out + OUT_ELEMS;

    static int smem_set = 0;
    if (!smem_set) {
        cudaFuncSetAttribute(k_gemm_proj, cudaFuncAttributeMaxDynamicSharedMemorySize, SMEMB);
        cudaFuncSetAttribute(k_attn_fused, cudaFuncAttributeMaxDynamicSharedMemorySize, SMEMB);
        cudaFuncSetAttribute(k_gemm_ctx,  cudaFuncAttributeMaxDynamicSharedMemorySize, SMEMB);
        cudaFuncSetAttribute(k_gemm_out,  cudaFuncAttributeMaxDynamicSharedMemorySize, SMEMB);
        smem_set = 1;
    }

    // launch order chosen so capture index 3 == k_gemm_proj
    k_cvt_w<<<dim3((WSZ / 4 + 255) / 256, 4), 256>>>(Wq, Wk, Wv, Wo);
    k_cvt_x<<<(OUT_ELEMS / 4 + 255) / 256, 256>>>(x);
    k_bucket<<<(Hh * Cc * Cc + 255) / 256, 256>>>(ds);

    k_gemm_proj<<<dim3(6, 384, 3), 256, SMEMB>>>(bq, bk, bv);
    k_transp<<<dim3(32, 8, 144), dim3(32, 8)>>>();
    k_attn_fused<<<dim3(4, PAIRS), 256, SMEMB>>>(rb, probs);
    k_gemm_ctx<<<dim3(8, 2, PAIRS), 256, SMEMB>>>();
    k_gemm_out<<<dim3(6, 384), 256, SMEMB>>>(bo, out);
}